// round 3
// baseline (speedup 1.0000x reference)
#include <cuda_runtime.h>
#include <math.h>

#define NN 100000
#define NE 1600000
#define C  128
#define OC 64
#define NG 64
#define GR 128      // gemm rows per block
#define GK 16       // gemm k-chunk

// ---------------- static device scratch (zero-initialized .bss) --------------
__device__ float g_bufA[(size_t)NN * C];
__device__ float g_bufB[(size_t)NN * C];
__device__ int   g_col[NE];
__device__ int   g_cnt[NN];        // in-degree (no self loop); zeroed by k_cleanup
__device__ int   g_rowptr[NN];
__device__ int   g_fillptr[NN];
__device__ float g_dinv[NN];
__device__ int   g_bsum[128];
__device__ int   g_gcnt[NG];       // zeroed by k_cleanup
__device__ int   g_goff[NG + 1];
__device__ float g_pool[NG * C];

// ---------------- helpers ----------------------------------------------------
__device__ __forceinline__ int detect64(const int* e32) {
    int is64 = 1;
    #pragma unroll
    for (int i = 0; i < 8; i++) if (e32[2 * i + 1] != 0) is64 = 0;
    return is64;
}

// idx 0: edge in-degree histogram + per-graph node histogram (counters pre-zeroed)
__global__ void k_hist_all(const void* ei, const void* bat, int E, int N) {
    int tid = blockIdx.x * blockDim.x + threadIdx.x;
    int stride = gridDim.x * blockDim.x;
    int is64 = detect64((const int*)ei);
    if (is64) {
        const long long* e = (const long long*)ei;
        for (int i = tid; i < E; i += stride)
            atomicAdd(&g_cnt[(int)e[(size_t)E + i]], 1);
        const long long* b = (const long long*)bat;
        for (int i = tid; i < N; i += stride) atomicAdd(&g_gcnt[(int)b[i]], 1);
    } else {
        const int* e = (const int*)ei;
        for (int i = tid; i < E; i += stride)
            atomicAdd(&g_cnt[e[E + i]], 1);
        const int* b = (const int*)bat;
        for (int i = tid; i < N; i += stride) atomicAdd(&g_gcnt[b[i]], 1);
    }
}

// idx 1: per-tile exclusive scan + dinv
__global__ void k_scan1(int n) {
    __shared__ int sh[1024];
    int i = blockIdx.x * 1024 + threadIdx.x;
    int v = (i < n) ? g_cnt[i] : 0;
    sh[threadIdx.x] = v;
    __syncthreads();
    for (int off = 1; off < 1024; off <<= 1) {
        int t = (threadIdx.x >= off) ? sh[threadIdx.x - off] : 0;
        __syncthreads();
        sh[threadIdx.x] += t;
        __syncthreads();
    }
    if (i < n) {
        g_rowptr[i] = sh[threadIdx.x] - v;
        g_dinv[i] = rsqrtf((float)(v + 1));
    }
    if (threadIdx.x == 1023) g_bsum[blockIdx.x] = sh[1023];
}

// idx 2
__global__ void k_scan2(int nb) {
    __shared__ int sh[128];
    int v = (threadIdx.x < nb) ? g_bsum[threadIdx.x] : 0;
    sh[threadIdx.x] = v;
    __syncthreads();
    for (int off = 1; off < 128; off <<= 1) {
        int t = (threadIdx.x >= off) ? sh[threadIdx.x - off] : 0;
        __syncthreads();
        sh[threadIdx.x] += t;
        __syncthreads();
    }
    if (threadIdx.x < nb) g_bsum[threadIdx.x] = sh[threadIdx.x] - v;
}

// idx 3 (PROFILED): Y = dinv .* (X @ W)   128x128 tile, 8x8 per thread
__global__ __launch_bounds__(256, 2) void k_gemm(
    const float* __restrict__ X, const float* __restrict__ W,
    float* __restrict__ Y, int n)
{
    __shared__ float As[GK][132];   // [k][row], pad to 132 (16B-aligned rows)
    __shared__ float Bs[GK][128];   // [k][col]
    int tid = threadIdx.x;
    int row0 = blockIdx.x * GR;

    int tx = tid & 15;     // cols [tx*8, tx*8+8)
    int ty = tid >> 4;     // rows [ty*8, ty*8+8)

    int lr = tid >> 2;           // X loader: row within tile (0..63, +64)
    int lk = (tid & 3) * 4;      // X loader: k offset within chunk
    int wk = tid >> 4;           // W loader: k row (0..15)
    int wc = (tid & 15) * 4;     // W loader: col (0..60, +64)

    float acc[8][8];
    #pragma unroll
    for (int i = 0; i < 8; i++)
        #pragma unroll
        for (int j = 0; j < 8; j++) acc[i][j] = 0.f;

    for (int kc = 0; kc < C; kc += GK) {
        __syncthreads();
        #pragma unroll
        for (int h = 0; h < 2; h++) {
            int r = lr + h * 64;
            int grow = row0 + r;
            float4 v = (grow < n) ? *(const float4*)&X[(size_t)grow * C + kc + lk]
                                  : make_float4(0.f, 0.f, 0.f, 0.f);
            As[lk + 0][r] = v.x; As[lk + 1][r] = v.y;
            As[lk + 2][r] = v.z; As[lk + 3][r] = v.w;
        }
        #pragma unroll
        for (int h = 0; h < 2; h++) {
            int c = wc + h * 64;
            *(float4*)&Bs[wk][c] = *(const float4*)&W[(size_t)(kc + wk) * C + c];
        }
        __syncthreads();
        #pragma unroll
        for (int k = 0; k < GK; k++) {
            float a[8], b[8];
            *(float4*)&a[0] = *(const float4*)&As[k][ty * 8];
            *(float4*)&a[4] = *(const float4*)&As[k][ty * 8 + 4];
            *(float4*)&b[0] = *(const float4*)&Bs[k][tx * 8];
            *(float4*)&b[4] = *(const float4*)&Bs[k][tx * 8 + 4];
            #pragma unroll
            for (int i = 0; i < 8; i++)
                #pragma unroll
                for (int j = 0; j < 8; j++)
                    acc[i][j] += a[i] * b[j];
        }
    }

    #pragma unroll
    for (int i = 0; i < 8; i++) {
        int row = row0 + ty * 8 + i;
        if (row < n) {
            float s = g_dinv[row];
            *(float4*)&Y[(size_t)row * C + tx * 8] =
                make_float4(acc[i][0] * s, acc[i][1] * s, acc[i][2] * s, acc[i][3] * s);
            *(float4*)&Y[(size_t)row * C + tx * 8 + 4] =
                make_float4(acc[i][4] * s, acc[i][5] * s, acc[i][6] * s, acc[i][7] * s);
        }
    }
}

// idx 4: finalize rowptr, init fillptr
__global__ void k_scan3(int n) {
    int i = blockIdx.x * blockDim.x + threadIdx.x;
    if (i < n) {
        int r = g_rowptr[i] + g_bsum[i >> 10];
        g_rowptr[i] = r;
        g_fillptr[i] = r;
    }
}

// idx 5: CSR fill
__global__ void k_fill(const void* ei, int E) {
    int tid = blockIdx.x * blockDim.x + threadIdx.x;
    int stride = gridDim.x * blockDim.x;
    int is64 = detect64((const int*)ei);
    if (is64) {
        const long long* e = (const long long*)ei;
        for (int i = tid; i < E; i += stride) {
            int d = (int)e[(size_t)E + i];
            int s = (int)e[i];
            g_col[atomicAdd(&g_fillptr[d], 1)] = s;
        }
    } else {
        const int* e = (const int*)ei;
        for (int i = tid; i < E; i += stride) {
            int d = e[E + i];
            int s = e[i];
            g_col[atomicAdd(&g_fillptr[d], 1)] = s;
        }
    }
}

// idx 6/8: h[i] = relu(dinv_i * (y_i + sum_nb y_s) + b), warp per node
__global__ __launch_bounds__(256) void k_agg(
    const float* __restrict__ Yin, const float* __restrict__ bias,
    float* __restrict__ Hout, int n)
{
    int node = (blockIdx.x * blockDim.x + threadIdx.x) >> 5;
    int lane = threadIdx.x & 31;
    if (node >= n) return;

    const float4* Y4 = (const float4*)Yin;
    float4 acc = Y4[(size_t)node * 32 + lane];      // self loop
    int e = g_rowptr[node];
    int end = e + g_cnt[node];

    for (; e + 8 <= end; e += 8) {
        int s[8];
        #pragma unroll
        for (int j = 0; j < 8; j++) s[j] = g_col[e + j];
        float4 v[8];
        #pragma unroll
        for (int j = 0; j < 8; j++) v[j] = Y4[(size_t)s[j] * 32 + lane];
        #pragma unroll
        for (int j = 0; j < 8; j++) {
            acc.x += v[j].x; acc.y += v[j].y;
            acc.z += v[j].z; acc.w += v[j].w;
        }
    }
    for (; e < end; e++) {
        float4 v = Y4[(size_t)g_col[e] * 32 + lane];
        acc.x += v.x; acc.y += v.y; acc.z += v.z; acc.w += v.w;
    }

    float di = g_dinv[node];
    float4 bv = ((const float4*)bias)[lane];
    float4 o;
    o.x = fmaxf(fmaf(di, acc.x, bv.x), 0.f);
    o.y = fmaxf(fmaf(di, acc.y, bv.y), 0.f);
    o.z = fmaxf(fmaf(di, acc.z, bv.z), 0.f);
    o.w = fmaxf(fmaf(di, acc.w, bv.w), 0.f);
    ((float4*)Hout)[(size_t)node * 32 + lane] = o;
}

// idx 9: graph offsets (smem serial scan, 64 elems)
__global__ void k_goff() {
    __shared__ int sh[NG];
    if (threadIdx.x < NG) sh[threadIdx.x] = g_gcnt[threadIdx.x];
    __syncthreads();
    if (threadIdx.x == 0) {
        int s = 0;
        for (int g = 0; g < NG; g++) { g_goff[g] = s; s += sh[g]; }
        g_goff[NG] = s;
    }
}

// idx 10: one block per graph, 8 row-lanes x 32 channel-quads
__global__ void k_pool(const float* __restrict__ H) {
    __shared__ float4 sh[8][32];
    int g = blockIdx.x;
    int rr = threadIdx.x >> 5;
    int c4 = threadIdx.x & 31;
    int s = g_goff[g], e = g_goff[g + 1];
    const float4* H4 = (const float4*)H;
    float4 acc = make_float4(0.f, 0.f, 0.f, 0.f);
    for (int r = s + rr; r < e; r += 8) {
        float4 v = H4[(size_t)r * 32 + c4];
        acc.x += v.x; acc.y += v.y; acc.z += v.z; acc.w += v.w;
    }
    sh[rr][c4] = acc;
    __syncthreads();
    if (rr == 0) {
        #pragma unroll
        for (int j = 1; j < 8; j++) {
            float4 v = sh[j][c4];
            acc.x += v.x; acc.y += v.y; acc.z += v.z; acc.w += v.w;
        }
        float inv = 1.0f / fmaxf((float)(e - s), 1.0f);
        ((float4*)g_pool)[g * 32 + c4] =
            make_float4(acc.x * inv, acc.y * inv, acc.z * inv, acc.w * inv);
    }
}

// idx 11
__global__ void k_head(const float* __restrict__ Wl,
                       const float* __restrict__ bl,
                       float* __restrict__ out)
{
    int g = blockIdx.x;
    int o = threadIdx.x;
    float acc = bl[o];
    #pragma unroll 4
    for (int k = 0; k < C; k++) acc += g_pool[g * C + k] * Wl[k * OC + o];
    out[g * OC + o] = acc;
}

// idx 12: restore zeroed counters for next replay (determinism)
__global__ void k_cleanup(int N) {
    int tid = blockIdx.x * blockDim.x + threadIdx.x;
    int stride = gridDim.x * blockDim.x;
    for (int i = tid; i < N; i += stride) g_cnt[i] = 0;
    if (tid < NG) g_gcnt[tid] = 0;
}

// ---------------- launch -----------------------------------------------------
extern "C" void kernel_launch(void* const* d_in, const int* in_sizes, int n_in,
                              void* d_out, int out_size) {
    const float* x   = (const float*)d_in[0];
    const void*  ei  = d_in[1];
    const void*  bat = d_in[2];
    const float* W1  = (const float*)d_in[3];
    const float* b1  = (const float*)d_in[4];
    const float* W2  = (const float*)d_in[5];
    const float* b2  = (const float*)d_in[6];
    const float* Wl  = (const float*)d_in[7];
    const float* bl  = (const float*)d_in[8];
    float* out = (float*)d_out;

    int N = in_sizes[0] / C;
    int E = in_sizes[1] / 2;
    int nb = (N + 1023) / 1024;
    int gb = (N + GR - 1) / GR;

    k_hist_all<<<1024, 256>>>(ei, bat, E, N);                 // 0
    k_scan1   <<<nb, 1024>>>(N);                              // 1
    k_scan2   <<<1, 128>>>(nb);                               // 2
    k_gemm    <<<gb, 256>>>(x, W1, g_bufA, N);                // 3  <-- profiled
    k_scan3   <<<(N + 255) / 256, 256>>>(N);                  // 4
    k_fill    <<<1024, 256>>>(ei, E);                         // 5
    k_agg     <<<(N * 32 + 255) / 256, 256>>>(g_bufA, b1, g_bufB, N);  // 6
    k_gemm    <<<gb, 256>>>(g_bufB, W2, g_bufA, N);           // 7
    k_agg     <<<(N * 32 + 255) / 256, 256>>>(g_bufA, b2, g_bufB, N);  // 8
    k_goff    <<<1, 64>>>();                                  // 9
    k_pool    <<<NG, 256>>>(g_bufB);                          // 10
    k_head    <<<NG, OC>>>(Wl, bl, out);                      // 11
    k_cleanup <<<256, 256>>>(N);                              // 12
}

// round 4
// speedup vs baseline: 1.9429x; 1.9429x over previous
#include <cuda_runtime.h>
#include <math.h>

#define NN 100000
#define NE 1600000
#define C  128
#define OC 64
#define NG 64

// ---------------- static device scratch (zero-initialized .bss) --------------
__device__ float g_bufA[(size_t)NN * C];
__device__ float g_bufB[(size_t)NN * C];
__device__ int   g_col[NE];
__device__ int   g_cnt[NN];        // in-degree (no self loop); re-zeroed by k_cleanup
__device__ int   g_rowptr[NN];
__device__ int   g_fillptr[NN];
__device__ float g_dinv[NN];
__device__ int   g_bsum[128];
__device__ int   g_gcnt[NG];       // re-zeroed by k_cleanup
__device__ int   g_goff[NG + 1];
__device__ float g_pool[NG * C];

__device__ __forceinline__ int detect64(const int* e32) {
    int is64 = 1;
    #pragma unroll
    for (int i = 0; i < 8; i++) if (e32[2 * i + 1] != 0) is64 = 0;
    return is64;
}

// idx 0: in-degree histogram + per-graph node histogram (counters pre-zeroed)
__global__ void k_hist_all(const void* ei, const void* bat, int E, int N) {
    int tid = blockIdx.x * blockDim.x + threadIdx.x;
    int stride = gridDim.x * blockDim.x;
    int is64 = detect64((const int*)ei);
    if (is64) {
        const long long* e = (const long long*)ei;
        for (int i = tid; i < E; i += stride)
            atomicAdd(&g_cnt[(int)e[(size_t)E + i]], 1);
        const long long* b = (const long long*)bat;
        for (int i = tid; i < N; i += stride) atomicAdd(&g_gcnt[(int)b[i]], 1);
    } else {
        const int* e = (const int*)ei;
        for (int i = tid; i < E; i += stride)
            atomicAdd(&g_cnt[e[E + i]], 1);
        const int* b = (const int*)bat;
        for (int i = tid; i < N; i += stride) atomicAdd(&g_gcnt[b[i]], 1);
    }
}

// idx 1: per-block exclusive scan of degrees + dinv
__global__ void k_scan1(int n) {
    __shared__ int sh[1024];
    int i = blockIdx.x * 1024 + threadIdx.x;
    int v = (i < n) ? g_cnt[i] : 0;
    sh[threadIdx.x] = v;
    __syncthreads();
    for (int off = 1; off < 1024; off <<= 1) {
        int t = (threadIdx.x >= off) ? sh[threadIdx.x - off] : 0;
        __syncthreads();
        sh[threadIdx.x] += t;
        __syncthreads();
    }
    if (i < n) {
        g_rowptr[i] = sh[threadIdx.x] - v;
        g_dinv[i] = rsqrtf((float)(v + 1));
    }
    if (threadIdx.x == 1023) g_bsum[blockIdx.x] = sh[1023];
}

// idx 2: finalize rowptr/fillptr (each block redundantly scans the 98 sums)
__global__ void k_scan23(int n) {
    __shared__ int sb[128];
    int nb = (n + 1023) >> 10;
    if (threadIdx.x < 128)
        sb[threadIdx.x] = (threadIdx.x < nb) ? g_bsum[threadIdx.x] : 0;
    __syncthreads();
    if (threadIdx.x == 0) {
        int s = 0;
        for (int b = 0; b < 128; b++) { int t = sb[b]; sb[b] = s; s += t; }
    }
    __syncthreads();
    int i = blockIdx.x * 1024 + threadIdx.x;
    if (i < n) {
        int r = g_rowptr[i] + sb[blockIdx.x];
        g_rowptr[i] = r;
        g_fillptr[i] = r;
    }
}

// idx 3 (PROFILED): CSR column fill via atomic cursors
__global__ void k_fill(const void* ei, int E) {
    int tid = blockIdx.x * blockDim.x + threadIdx.x;
    int stride = gridDim.x * blockDim.x;
    int is64 = detect64((const int*)ei);
    if (is64) {
        const long long* e = (const long long*)ei;
        for (int i = tid; i < E; i += stride) {
            int d = (int)e[(size_t)E + i];
            int s = (int)e[i];
            g_col[atomicAdd(&g_fillptr[d], 1)] = s;
        }
    } else {
        const int* e = (const int*)ei;
        for (int i = tid; i < E; i += stride) {
            int d = e[E + i];
            int s = e[i];
            g_col[atomicAdd(&g_fillptr[d], 1)] = s;
        }
    }
}

// idx 4/6: z_i = dinv_i * (dinv_i*x_i + sum_j dinv_j*x_j)   (aggregate-first)
// warp per node, lane owns 4 channels
__global__ __launch_bounds__(256) void k_agg(
    const float* __restrict__ Xin, float* __restrict__ Zout, int n)
{
    int node = (blockIdx.x * blockDim.x + threadIdx.x) >> 5;
    int lane = threadIdx.x & 31;
    if (node >= n) return;

    const float4* X4 = (const float4*)Xin;
    float di = g_dinv[node];
    float4 s4 = X4[(size_t)node * 32 + lane];
    float4 acc = make_float4(s4.x * di, s4.y * di, s4.z * di, s4.w * di);

    int e = g_rowptr[node];
    int end = e + g_cnt[node];

    for (; e + 8 <= end; e += 8) {
        int s[8];
        #pragma unroll
        for (int j = 0; j < 8; j++) s[j] = g_col[e + j];
        float w[8];
        #pragma unroll
        for (int j = 0; j < 8; j++) w[j] = g_dinv[s[j]];
        float4 v[8];
        #pragma unroll
        for (int j = 0; j < 8; j++) v[j] = X4[(size_t)s[j] * 32 + lane];
        #pragma unroll
        for (int j = 0; j < 8; j++) {
            acc.x = fmaf(w[j], v[j].x, acc.x);
            acc.y = fmaf(w[j], v[j].y, acc.y);
            acc.z = fmaf(w[j], v[j].z, acc.z);
            acc.w = fmaf(w[j], v[j].w, acc.w);
        }
    }
    for (; e < end; e++) {
        int s = g_col[e];
        float w = g_dinv[s];
        float4 v = X4[(size_t)s * 32 + lane];
        acc.x = fmaf(w, v.x, acc.x);
        acc.y = fmaf(w, v.y, acc.y);
        acc.z = fmaf(w, v.z, acc.z);
        acc.w = fmaf(w, v.w, acc.w);
    }

    float4 o;
    o.x = di * acc.x; o.y = di * acc.y;
    o.z = di * acc.z; o.w = di * acc.w;
    ((float4*)Zout)[(size_t)node * 32 + lane] = o;
}

// idx 5/7: H = relu(Z @ W + b)   64-row tile, full W in smem (round-2 config)
__global__ __launch_bounds__(256, 2) void k_gemm(
    const float* __restrict__ Z, const float* __restrict__ W,
    const float* __restrict__ bias, float* __restrict__ H, int n)
{
    __shared__ float Ws[C * C];      // 64 KB
    __shared__ float Zs[64 * C];     // 32 KB
    int tid = threadIdx.x;
    int row0 = blockIdx.x * 64;

    for (int i = tid; i < C * C; i += 256) Ws[i] = W[i];
    for (int i = tid; i < 64 * C; i += 256) {
        int r = row0 + (i >> 7);
        Zs[i] = (r < n) ? Z[(size_t)r * C + (i & 127)] : 0.0f;
    }
    __syncthreads();

    int tn = tid & 31;    // cols [tn*4, tn*4+4)
    int tm = tid >> 5;    // rows [tm*8, tm*8+8)
    float acc[8][4];
    #pragma unroll
    for (int r = 0; r < 8; r++)
        #pragma unroll
        for (int c = 0; c < 4; c++) acc[r][c] = 0.0f;

    #pragma unroll 4
    for (int k = 0; k < C; k++) {
        float4 wv = *(const float4*)&Ws[k * C + tn * 4];
        #pragma unroll
        for (int r = 0; r < 8; r++) {
            float zv = Zs[(tm * 8 + r) * C + k];
            acc[r][0] += zv * wv.x;
            acc[r][1] += zv * wv.y;
            acc[r][2] += zv * wv.z;
            acc[r][3] += zv * wv.w;
        }
    }

    float4 bv = ((const float4*)bias)[tn];
    #pragma unroll
    for (int r = 0; r < 8; r++) {
        int row = row0 + tm * 8 + r;
        if (row < n) {
            float4 o;
            o.x = fmaxf(acc[r][0] + bv.x, 0.f);
            o.y = fmaxf(acc[r][1] + bv.y, 0.f);
            o.z = fmaxf(acc[r][2] + bv.z, 0.f);
            o.w = fmaxf(acc[r][3] + bv.w, 0.f);
            *(float4*)&H[(size_t)row * C + tn * 4] = o;
        }
    }
}

// idx 8
__global__ void k_goff() {
    __shared__ int sh[NG];
    if (threadIdx.x < NG) sh[threadIdx.x] = g_gcnt[threadIdx.x];
    __syncthreads();
    if (threadIdx.x == 0) {
        int s = 0;
        for (int g = 0; g < NG; g++) { g_goff[g] = s; s += sh[g]; }
        g_goff[NG] = s;
    }
}

// idx 9: one block per graph
__global__ void k_pool(const float* __restrict__ H) {
    __shared__ float4 sh[8][32];
    int g = blockIdx.x;
    int rr = threadIdx.x >> 5;
    int c4 = threadIdx.x & 31;
    int s = g_goff[g], e = g_goff[g + 1];
    const float4* H4 = (const float4*)H;
    float4 acc = make_float4(0.f, 0.f, 0.f, 0.f);
    for (int r = s + rr; r < e; r += 8) {
        float4 v = H4[(size_t)r * 32 + c4];
        acc.x += v.x; acc.y += v.y; acc.z += v.z; acc.w += v.w;
    }
    sh[rr][c4] = acc;
    __syncthreads();
    if (rr == 0) {
        #pragma unroll
        for (int j = 1; j < 8; j++) {
            float4 v = sh[j][c4];
            acc.x += v.x; acc.y += v.y; acc.z += v.z; acc.w += v.w;
        }
        float inv = 1.0f / fmaxf((float)(e - s), 1.0f);
        ((float4*)g_pool)[g * 32 + c4] =
            make_float4(acc.x * inv, acc.y * inv, acc.z * inv, acc.w * inv);
    }
}

// idx 10
__global__ void k_head(const float* __restrict__ Wl,
                       const float* __restrict__ bl,
                       float* __restrict__ out)
{
    int g = blockIdx.x;
    int o = threadIdx.x;
    float acc = bl[o];
    #pragma unroll 4
    for (int k = 0; k < C; k++) acc += g_pool[g * C + k] * Wl[k * OC + o];
    out[g * OC + o] = acc;
}

// idx 11: restore zeroed counters for next replay
__global__ void k_cleanup(int N) {
    int tid = blockIdx.x * blockDim.x + threadIdx.x;
    int stride = gridDim.x * blockDim.x;
    for (int i = tid; i < N; i += stride) g_cnt[i] = 0;
    if (tid < NG) g_gcnt[tid] = 0;
}

// ---------------- launch -----------------------------------------------------
extern "C" void kernel_launch(void* const* d_in, const int* in_sizes, int n_in,
                              void* d_out, int out_size) {
    const float* x   = (const float*)d_in[0];
    const void*  ei  = d_in[1];
    const void*  bat = d_in[2];
    const float* W1  = (const float*)d_in[3];
    const float* b1  = (const float*)d_in[4];
    const float* W2  = (const float*)d_in[5];
    const float* b2  = (const float*)d_in[6];
    const float* Wl  = (const float*)d_in[7];
    const float* bl  = (const float*)d_in[8];
    float* out = (float*)d_out;

    int N = in_sizes[0] / C;
    int E = in_sizes[1] / 2;
    int nb = (N + 1023) / 1024;
    int gb = (N + 63) / 64;

    k_hist_all<<<1024, 256>>>(ei, bat, E, N);                        // 0
    k_scan1   <<<nb, 1024>>>(N);                                     // 1
    k_scan23  <<<nb, 1024>>>(N);                                     // 2
    k_fill    <<<1024, 256>>>(ei, E);                                // 3  <-- profiled
    k_agg     <<<(N * 32 + 255) / 256, 256>>>(x, g_bufA, N);         // 4
    k_gemm    <<<gb, 256>>>(g_bufA, W1, b1, g_bufB, N);              // 5
    k_agg     <<<(N * 32 + 255) / 256, 256>>>(g_bufB, g_bufA, N);    // 6
    k_gemm    <<<gb, 256>>>(g_bufA, W2, b2, g_bufB, N);              // 7
    k_goff    <<<1, 64>>>();                                         // 8
    k_pool    <<<NG, 256>>>(g_bufB);                                 // 9
    k_head    <<<NG, OC>>>(Wl, bl, out);                             // 10
    k_cleanup <<<256, 256>>>(N);                                     // 11
}